// round 3
// baseline (speedup 1.0000x reference)
#include <cuda_runtime.h>

// IoU3DLoss: per-pair rotated 3D IoU -> mean((1-iou)*weight)
// Single fused kernel:
//  - smem-staged coalesced loads of the 7-float box records
//  - branch-free Green's-theorem intersection area (8 Liang-Barsky slab clips)
//  - fast MUFU sincos (__sincosf): abs err ~2^-21, negligible at the mean
//  - block partials + "last block finalizes" deterministic reduction (no 2nd launch)

constexpr int BLOCK = 256;
constexpr int MAX_PARTIALS = 8192;

__device__ float g_partial[MAX_PARTIALS];
__device__ unsigned int g_ticket = 0;

// t-interval of u0 + t*du within |coord| <= W. Branchless via IEEE inf.
__device__ __forceinline__ void slab_clip(float u0, float du, float W,
                                          float& lo, float& hi)
{
    float inv = __fdividef(1.0f, du);   // du==0 -> +/-inf; interval stays correct
    float ta = (-W - u0) * inv;
    float tb = ( W - u0) * inv;
    lo = fminf(ta, tb);
    hi = fmaxf(ta, tb);
}

// Clip segment (p0, p0+d) to axis box [+-W,+-H] given box-local coords (u0,v0,du,dv);
// endpoints evaluated in the caller's frame; returns cross(start, end).
__device__ __forceinline__ float clipped_cross(float u0, float v0, float du, float dv,
                                               float W, float H,
                                               float p0x, float p0y, float dx, float dy)
{
    float lo1, hi1, lo2, hi2;
    slab_clip(u0, du, W, lo1, hi1);
    slab_clip(v0, dv, H, lo2, hi2);
    float tmin = fmaxf(fmaxf(lo1, lo2), 0.0f);
    float tmax = fminf(fminf(hi1, hi2), 1.0f);
    bool valid = (tmax > tmin);
    float ax = fmaf(tmin, dx, p0x), ay = fmaf(tmin, dy, p0y);
    float bx = fmaf(tmax, dx, p0x), by = fmaf(tmax, dy, p0y);
    float cr = ax * by - ay * bx;
    return valid ? cr : 0.0f;
}

__device__ __forceinline__ float pair_loss(const float* __restrict__ b1,
                                           const float* __restrict__ b2,
                                           float wgt)
{
    float x1 = b1[0], y1 = b1[1], z1 = b1[2], w1 = b1[3], h1 = b1[4], d1 = b1[5], a1 = b1[6];
    float x2 = b2[0], y2 = b2[1], z2 = b2[2], w2 = b2[3], h2 = b2[4], d2 = b2[5], a2 = b2[6];

    // B(target) local frame: B = axis box [+-W2,+-H2]; A at rel angle ar = a1-a2.
    float s2, c2; __sincosf(a2, &s2, &c2);
    float sr, cr; __sincosf(a1 - a2, &sr, &cr);

    float dx0 = x1 - x2, dy0 = y1 - y2;
    float cx =  c2 * dx0 + s2 * dy0;
    float cy = -s2 * dx0 + c2 * dy0;

    float W1 = 0.5f * w1, H1 = 0.5f * h1;
    float W2 = 0.5f * w2, H2 = 0.5f * h2;

    float ex = cr * W1, ey = sr * W1;    // A half-edge along its local x (in B frame)
    float fx = -sr * H1, fy = cr * H1;   // A half-edge along its local y

    // A corners, CCW: c+e+f, c-e+f, c-e-f, c+e-f
    float Ax0 = cx + ex + fx, Ay0 = cy + ey + fy;
    float Ax1 = cx - ex + fx, Ay1 = cy - ey + fy;
    float Ax2 = cx - ex - fx, Ay2 = cy - ey - fy;
    float Ax3 = cx + ex - fx, Ay3 = cy + ey - fy;

    float area2 = 0.0f;

    // Edges of A clipped against box B (coords already in B frame)
    {
        float dxe, dye;
        dxe = Ax1 - Ax0; dye = Ay1 - Ay0;
        area2 += clipped_cross(Ax0, Ay0, dxe, dye, W2, H2, Ax0, Ay0, dxe, dye);
        dxe = Ax2 - Ax1; dye = Ay2 - Ay1;
        area2 += clipped_cross(Ax1, Ay1, dxe, dye, W2, H2, Ax1, Ay1, dxe, dye);
        dxe = Ax3 - Ax2; dye = Ay3 - Ay2;
        area2 += clipped_cross(Ax2, Ay2, dxe, dye, W2, H2, Ax2, Ay2, dxe, dye);
        dxe = Ax0 - Ax3; dye = Ay0 - Ay3;
        area2 += clipped_cross(Ax3, Ay3, dxe, dye, W2, H2, Ax3, Ay3, dxe, dye);
    }

    // Edges of B clipped against box A (transform into A-local coords)
    {
        const float Bx[4] = { W2, -W2, -W2,  W2 };
        const float By[4] = { H2,  H2, -H2, -H2 };
        #pragma unroll
        for (int k = 0; k < 4; k++) {
            float p0x = Bx[k], p0y = By[k];
            float p1x = Bx[(k + 1) & 3], p1y = By[(k + 1) & 3];
            float dxe = p1x - p0x, dye = p1y - p0y;
            float rx = p0x - cx, ry = p0y - cy;
            float u0 =  cr * rx + sr * ry;
            float v0 = -sr * rx + cr * ry;
            float du =  cr * dxe + sr * dye;
            float dv = -sr * dxe + cr * dye;
            area2 += clipped_cross(u0, v0, du, dv, W1, H1, p0x, p0y, dxe, dye);
        }
    }

    float inter2d = 0.5f * fabsf(area2);

    float zmax = fminf(z1 + 0.5f * d1, z2 + 0.5f * d2);
    float zmin = fmaxf(z1 - 0.5f * d1, z2 - 0.5f * d2);
    float inter3d = inter2d * fmaxf(zmax - zmin, 0.0f);

    float v1 = w1 * h1 * d1;
    float v2 = w2 * h2 * d2;
    float iou = inter3d / (v1 + v2 - inter3d + 1e-8f);

    return (1.0f - iou) * wgt;
}

__global__ void __launch_bounds__(BLOCK)
iou3d_fused_kernel(const float* __restrict__ pred,
                   const float* __restrict__ target,
                   const float* __restrict__ weight,
                   float* __restrict__ out,
                   int N, float inv_n, int nblocks)
{
    __shared__ float sp[BLOCK * 7];
    __shared__ float st[BLOCK * 7];
    __shared__ float swarp[BLOCK / 32];
    __shared__ bool s_last;

    float loss = 0.0f;

    for (int base = blockIdx.x * BLOCK; base < N; base += nblocks * BLOCK) {
        int nrow = min(BLOCK, N - base);
        int nflt = nrow * 7;
        const float* pb = pred   + (size_t)base * 7;
        const float* tb = target + (size_t)base * 7;

        __syncthreads();   // protect smem from previous iteration's readers
        for (int j = threadIdx.x; j < nflt; j += BLOCK) {
            sp[j] = pb[j];
            st[j] = tb[j];
        }
        __syncthreads();

        int r = threadIdx.x;
        if (r < nrow)
            loss += pair_loss(sp + r * 7, st + r * 7, weight[base + r]);
    }

    // Block reduction
    #pragma unroll
    for (int off = 16; off > 0; off >>= 1)
        loss += __shfl_xor_sync(0xffffffffu, loss, off);
    if ((threadIdx.x & 31) == 0) swarp[threadIdx.x >> 5] = loss;
    __syncthreads();
    if (threadIdx.x < BLOCK / 32) {
        float v = swarp[threadIdx.x];
        #pragma unroll
        for (int off = (BLOCK / 64); off > 0; off >>= 1)
            v += __shfl_xor_sync(0xffu, v, off);
        if (threadIdx.x == 0) {
            g_partial[blockIdx.x] = v;
            __threadfence();
            unsigned int t = atomicAdd(&g_ticket, 1u);
            s_last = (t == (unsigned int)(nblocks - 1));
        }
    }
    __syncthreads();

    // Last block to finish sums all partials (fixed order -> deterministic)
    if (s_last) {
        float s = 0.0f;
        for (int k = threadIdx.x; k < nblocks; k += BLOCK)
            s += g_partial[k];
        #pragma unroll
        for (int off = 16; off > 0; off >>= 1)
            s += __shfl_xor_sync(0xffffffffu, s, off);
        if ((threadIdx.x & 31) == 0) swarp[threadIdx.x >> 5] = s;
        __syncthreads();
        if (threadIdx.x == 0) {
            float v = 0.0f;
            #pragma unroll
            for (int w = 0; w < BLOCK / 32; w++) v += swarp[w];
            out[0] = v * inv_n;
            g_ticket = 0;            // reset for next graph replay
            __threadfence();
        }
    }
}

extern "C" void kernel_launch(void* const* d_in, const int* in_sizes, int n_in,
                              void* d_out, int out_size)
{
    const float* pred   = (const float*)d_in[0];
    const float* target = (const float*)d_in[1];
    const float* weight = (const float*)d_in[2];
    int N = in_sizes[2];

    int grid = (N + BLOCK - 1) / BLOCK;
    if (grid > MAX_PARTIALS) grid = MAX_PARTIALS;   // N=1M -> 4096 blocks

    iou3d_fused_kernel<<<grid, BLOCK>>>(pred, target, weight, (float*)d_out,
                                        N, 1.0f / (float)N, grid);
}

// round 4
// speedup vs baseline: 1.6231x; 1.6231x over previous
#include <cuda_runtime.h>

// IoU3DLoss: per-pair rotated 3D IoU -> mean((1-iou)*weight)
// Single fused kernel:
//  - direct per-thread LDG of the 7-float records (ptxas front-batches them -> high MLP)
//  - branch-free Green's-theorem intersection area (8 Liang-Barsky slab clips)
//  - MUFU __sincosf only (abs err ~2^-21; negligible in the 1M-element mean)
//  - block partials + "last block finalizes" deterministic reduction (single launch)

constexpr int BLOCK = 256;
constexpr int MAX_PARTIALS = 8192;

__device__ float g_partial[MAX_PARTIALS];
__device__ unsigned int g_ticket = 0;

// t-interval of u0 + t*du within |coord| <= W. Branchless via IEEE inf.
__device__ __forceinline__ void slab_clip(float u0, float du, float W,
                                          float& lo, float& hi)
{
    float inv = __fdividef(1.0f, du);   // du==0 -> +/-inf; interval stays correct
    float ta = (-W - u0) * inv;
    float tb = ( W - u0) * inv;
    lo = fminf(ta, tb);
    hi = fmaxf(ta, tb);
}

// Clip segment (p0, p0+d) to axis box [+-W,+-H] given box-local coords (u0,v0,du,dv);
// endpoints evaluated in the caller's frame; returns cross(start, end).
__device__ __forceinline__ float clipped_cross(float u0, float v0, float du, float dv,
                                               float W, float H,
                                               float p0x, float p0y, float dx, float dy)
{
    float lo1, hi1, lo2, hi2;
    slab_clip(u0, du, W, lo1, hi1);
    slab_clip(v0, dv, H, lo2, hi2);
    float tmin = fmaxf(fmaxf(lo1, lo2), 0.0f);
    float tmax = fminf(fminf(hi1, hi2), 1.0f);
    bool valid = (tmax > tmin);
    float ax = fmaf(tmin, dx, p0x), ay = fmaf(tmin, dy, p0y);
    float bx = fmaf(tmax, dx, p0x), by = fmaf(tmax, dy, p0y);
    float cr = ax * by - ay * bx;
    return valid ? cr : 0.0f;
}

__global__ void __launch_bounds__(BLOCK)
iou3d_fused_kernel(const float* __restrict__ pred,
                   const float* __restrict__ target,
                   const float* __restrict__ weight,
                   float* __restrict__ out,
                   int N, float inv_n, int nblocks)
{
    __shared__ float swarp[BLOCK / 32];
    __shared__ bool s_last;

    int i = blockIdx.x * BLOCK + threadIdx.x;
    float loss = 0.0f;

    if (i < N) {
        const float* b1 = pred   + (size_t)i * 7;
        const float* b2 = target + (size_t)i * 7;
        float x1 = b1[0], y1 = b1[1], z1 = b1[2], w1 = b1[3], h1 = b1[4], d1 = b1[5], a1 = b1[6];
        float x2 = b2[0], y2 = b2[1], z2 = b2[2], w2 = b2[3], h2 = b2[4], d2 = b2[5], a2 = b2[6];
        float wgt = weight[i];

        // B(target) local frame: B = axis box [+-W2,+-H2]; A at rel angle ar = a1-a2.
        float s2, c2; __sincosf(a2, &s2, &c2);
        float sr, cr; __sincosf(a1 - a2, &sr, &cr);

        float dx0 = x1 - x2, dy0 = y1 - y2;
        float cx =  c2 * dx0 + s2 * dy0;
        float cy = -s2 * dx0 + c2 * dy0;

        float W1 = 0.5f * w1, H1 = 0.5f * h1;
        float W2 = 0.5f * w2, H2 = 0.5f * h2;

        float ex = cr * W1, ey = sr * W1;    // A half-edge along its local x (B frame)
        float fx = -sr * H1, fy = cr * H1;   // A half-edge along its local y

        // A corners, CCW: c+e+f, c-e+f, c-e-f, c+e-f
        float Ax0 = cx + ex + fx, Ay0 = cy + ey + fy;
        float Ax1 = cx - ex + fx, Ay1 = cy - ey + fy;
        float Ax2 = cx - ex - fx, Ay2 = cy - ey - fy;
        float Ax3 = cx + ex - fx, Ay3 = cy + ey - fy;

        float area2 = 0.0f;

        // Edges of A clipped against box B (coords already in B frame)
        {
            float dxe, dye;
            dxe = Ax1 - Ax0; dye = Ay1 - Ay0;
            area2 += clipped_cross(Ax0, Ay0, dxe, dye, W2, H2, Ax0, Ay0, dxe, dye);
            dxe = Ax2 - Ax1; dye = Ay2 - Ay1;
            area2 += clipped_cross(Ax1, Ay1, dxe, dye, W2, H2, Ax1, Ay1, dxe, dye);
            dxe = Ax3 - Ax2; dye = Ay3 - Ay2;
            area2 += clipped_cross(Ax2, Ay2, dxe, dye, W2, H2, Ax2, Ay2, dxe, dye);
            dxe = Ax0 - Ax3; dye = Ay0 - Ay3;
            area2 += clipped_cross(Ax3, Ay3, dxe, dye, W2, H2, Ax3, Ay3, dxe, dye);
        }

        // Edges of B clipped against box A (transform into A-local coords; the
        // constant +-W2/+-H2 corner table folds at compile time)
        {
            const float Bx[4] = { W2, -W2, -W2,  W2 };
            const float By[4] = { H2,  H2, -H2, -H2 };
            #pragma unroll
            for (int k = 0; k < 4; k++) {
                float p0x = Bx[k], p0y = By[k];
                float p1x = Bx[(k + 1) & 3], p1y = By[(k + 1) & 3];
                float dxe = p1x - p0x, dye = p1y - p0y;
                float rx = p0x - cx, ry = p0y - cy;
                float u0 =  cr * rx + sr * ry;
                float v0 = -sr * rx + cr * ry;
                float du =  cr * dxe + sr * dye;
                float dv = -sr * dxe + cr * dye;
                area2 += clipped_cross(u0, v0, du, dv, W1, H1, p0x, p0y, dxe, dye);
            }
        }

        float inter2d = 0.5f * fabsf(area2);

        float zmax = fminf(z1 + 0.5f * d1, z2 + 0.5f * d2);
        float zmin = fmaxf(z1 - 0.5f * d1, z2 - 0.5f * d2);
        float inter3d = inter2d * fmaxf(zmax - zmin, 0.0f);

        float v1 = w1 * h1 * d1;
        float v2 = w2 * h2 * d2;
        float iou = inter3d / (v1 + v2 - inter3d + 1e-8f);

        loss = (1.0f - iou) * wgt;
    }

    // Block reduction: warp shuffle -> shared -> one partial per block
    #pragma unroll
    for (int off = 16; off > 0; off >>= 1)
        loss += __shfl_xor_sync(0xffffffffu, loss, off);
    if ((threadIdx.x & 31) == 0) swarp[threadIdx.x >> 5] = loss;
    __syncthreads();
    if (threadIdx.x < BLOCK / 32) {
        float v = swarp[threadIdx.x];
        #pragma unroll
        for (int off = (BLOCK / 64); off > 0; off >>= 1)
            v += __shfl_xor_sync(0xffu, v, off);
        if (threadIdx.x == 0) {
            g_partial[blockIdx.x] = v;
            __threadfence();
            unsigned int t = atomicAdd(&g_ticket, 1u);
            s_last = (t == (unsigned int)(nblocks - 1));
        }
    }
    __syncthreads();

    // Last block to finish sums all partials (fixed order -> deterministic)
    if (s_last) {
        float s = 0.0f;
        for (int k = threadIdx.x; k < nblocks; k += BLOCK)
            s += g_partial[k];
        #pragma unroll
        for (int off = 16; off > 0; off >>= 1)
            s += __shfl_xor_sync(0xffffffffu, s, off);
        if ((threadIdx.x & 31) == 0) swarp[threadIdx.x >> 5] = s;
        __syncthreads();
        if (threadIdx.x == 0) {
            float v = 0.0f;
            #pragma unroll
            for (int w = 0; w < BLOCK / 32; w++) v += swarp[w];
            out[0] = v * inv_n;
            g_ticket = 0;            // reset for next graph replay
            __threadfence();
        }
    }
}

extern "C" void kernel_launch(void* const* d_in, const int* in_sizes, int n_in,
                              void* d_out, int out_size)
{
    const float* pred   = (const float*)d_in[0];
    const float* target = (const float*)d_in[1];
    const float* weight = (const float*)d_in[2];
    int N = in_sizes[2];

    int grid = (N + BLOCK - 1) / BLOCK;
    if (grid > MAX_PARTIALS) grid = MAX_PARTIALS;   // N=1M -> 4096 blocks

    iou3d_fused_kernel<<<grid, BLOCK>>>(pred, target, weight, (float*)d_out,
                                        N, 1.0f / (float)N, grid);
}

// round 5
// speedup vs baseline: 1.7798x; 1.0965x over previous
#include <cuda_runtime.h>

// IoU3DLoss: per-pair rotated 3D IoU -> mean((1-iou)*weight)
// Single kernel, fence-free deterministic reduction:
//  - direct per-thread LDG of the 7-float records (front-batched -> high MLP)
//  - branch-free Green's-theorem intersection area (8 Liang-Barsky slab clips)
//  - MUFU __sincosf (abs err ~2^-21; negligible in the 1M-element mean)
//  - per-block partial -> fixed-point u64, accumulated with ONE packed atomicAdd:
//      bits [0,44)  : sum * 2^23   (integer adds are associative -> deterministic)
//      bits [44,64) : block-completion counter
//    The atomic's return value gives the last block the full sum; no __threadfence
//    (avoids CCTL.IVALL L1 flushes that hurt co-resident blocks' record-load reuse).

constexpr int BLOCK = 256;
constexpr double FP_SCALE = 8388608.0;            // 2^23
constexpr unsigned long long SUM_MASK = (1ull << 44) - 1ull;
constexpr unsigned long long CNT_ONE  = 1ull << 44;

__device__ unsigned long long g_acc = 0ull;       // reset by last block each launch

// t-interval of u0 + t*du within |coord| <= W. Branchless via IEEE inf.
__device__ __forceinline__ void slab_clip(float u0, float du, float W,
                                          float& lo, float& hi)
{
    float inv = __fdividef(1.0f, du);   // du==0 -> +/-inf; interval stays correct
    float ta = (-W - u0) * inv;
    float tb = ( W - u0) * inv;
    lo = fminf(ta, tb);
    hi = fmaxf(ta, tb);
}

// Clip segment (p0, p0+d) to axis box [+-W,+-H] given box-local coords (u0,v0,du,dv);
// endpoints evaluated in the caller's frame; returns cross(start, end).
__device__ __forceinline__ float clipped_cross(float u0, float v0, float du, float dv,
                                               float W, float H,
                                               float p0x, float p0y, float dx, float dy)
{
    float lo1, hi1, lo2, hi2;
    slab_clip(u0, du, W, lo1, hi1);
    slab_clip(v0, dv, H, lo2, hi2);
    float tmin = fmaxf(fmaxf(lo1, lo2), 0.0f);
    float tmax = fminf(fminf(hi1, hi2), 1.0f);
    bool valid = (tmax > tmin);
    float ax = fmaf(tmin, dx, p0x), ay = fmaf(tmin, dy, p0y);
    float bx = fmaf(tmax, dx, p0x), by = fmaf(tmax, dy, p0y);
    float cr = ax * by - ay * bx;
    return valid ? cr : 0.0f;
}

__global__ void __launch_bounds__(BLOCK)
iou3d_fused_kernel(const float* __restrict__ pred,
                   const float* __restrict__ target,
                   const float* __restrict__ weight,
                   float* __restrict__ out,
                   int N, float inv_n, int nblocks)
{
    __shared__ float swarp[BLOCK / 32];

    unsigned int i = blockIdx.x * BLOCK + threadIdx.x;
    float loss = 0.0f;

    if ((int)i < N) {
        const float* b1 = pred   + 7u * i;
        const float* b2 = target + 7u * i;
        float x1 = b1[0], y1 = b1[1], z1 = b1[2], w1 = b1[3], h1 = b1[4], d1 = b1[5], a1 = b1[6];
        float x2 = b2[0], y2 = b2[1], z2 = b2[2], w2 = b2[3], h2 = b2[4], d2 = b2[5], a2 = b2[6];
        float wgt = weight[i];

        // B(target) local frame: B = axis box [+-W2,+-H2]; A at rel angle ar = a1-a2.
        float s2, c2; __sincosf(a2, &s2, &c2);
        float sr, cr; __sincosf(a1 - a2, &sr, &cr);

        float dx0 = x1 - x2, dy0 = y1 - y2;
        float cx =  c2 * dx0 + s2 * dy0;
        float cy = -s2 * dx0 + c2 * dy0;

        float W1 = 0.5f * w1, H1 = 0.5f * h1;
        float W2 = 0.5f * w2, H2 = 0.5f * h2;

        float ex = cr * W1, ey = sr * W1;    // A half-edge along its local x (B frame)
        float fx = -sr * H1, fy = cr * H1;   // A half-edge along its local y

        // A corners, CCW: c+e+f, c-e+f, c-e-f, c+e-f
        float Ax0 = cx + ex + fx, Ay0 = cy + ey + fy;
        float Ax1 = cx - ex + fx, Ay1 = cy - ey + fy;
        float Ax2 = cx - ex - fx, Ay2 = cy - ey - fy;
        float Ax3 = cx + ex - fx, Ay3 = cy + ey - fy;

        float area2 = 0.0f;

        // Edges of A clipped against box B (coords already in B frame)
        {
            float dxe, dye;
            dxe = Ax1 - Ax0; dye = Ay1 - Ay0;
            area2 += clipped_cross(Ax0, Ay0, dxe, dye, W2, H2, Ax0, Ay0, dxe, dye);
            dxe = Ax2 - Ax1; dye = Ay2 - Ay1;
            area2 += clipped_cross(Ax1, Ay1, dxe, dye, W2, H2, Ax1, Ay1, dxe, dye);
            dxe = Ax3 - Ax2; dye = Ay3 - Ay2;
            area2 += clipped_cross(Ax2, Ay2, dxe, dye, W2, H2, Ax2, Ay2, dxe, dye);
            dxe = Ax0 - Ax3; dye = Ay0 - Ay3;
            area2 += clipped_cross(Ax3, Ay3, dxe, dye, W2, H2, Ax3, Ay3, dxe, dye);
        }

        // Edges of B clipped against box A (constant corner table folds at compile time)
        {
            const float Bx[4] = { W2, -W2, -W2,  W2 };
            const float By[4] = { H2,  H2, -H2, -H2 };
            #pragma unroll
            for (int k = 0; k < 4; k++) {
                float p0x = Bx[k], p0y = By[k];
                float p1x = Bx[(k + 1) & 3], p1y = By[(k + 1) & 3];
                float dxe = p1x - p0x, dye = p1y - p0y;
                float rx = p0x - cx, ry = p0y - cy;
                float u0 =  cr * rx + sr * ry;
                float v0 = -sr * rx + cr * ry;
                float du =  cr * dxe + sr * dye;
                float dv = -sr * dxe + cr * dye;
                area2 += clipped_cross(u0, v0, du, dv, W1, H1, p0x, p0y, dxe, dye);
            }
        }

        float inter2d = 0.5f * fabsf(area2);

        float zmax = fminf(z1 + 0.5f * d1, z2 + 0.5f * d2);
        float zmin = fmaxf(z1 - 0.5f * d1, z2 - 0.5f * d2);
        float inter3d = inter2d * fmaxf(zmax - zmin, 0.0f);

        float v1 = w1 * h1 * d1;
        float v2 = w2 * h2 * d2;
        float iou = inter3d / (v1 + v2 - inter3d + 1e-8f);

        loss = (1.0f - iou) * wgt;
    }

    // Block reduction: warp shuffle -> shared -> warp 0
    #pragma unroll
    for (int off = 16; off > 0; off >>= 1)
        loss += __shfl_xor_sync(0xffffffffu, loss, off);
    if ((threadIdx.x & 31) == 0) swarp[threadIdx.x >> 5] = loss;
    __syncthreads();

    if (threadIdx.x == 0) {
        float partial = 0.0f;
        #pragma unroll
        for (int w = 0; w < BLOCK / 32; w++) partial += swarp[w];

        // Fixed-point encode (deterministic) + packed completion counter
        unsigned long long v =
            (unsigned long long)((double)partial * FP_SCALE + 0.5) | CNT_ONE;
        unsigned long long old = atomicAdd(&g_acc, v);

        if ((old >> 44) == (unsigned long long)(nblocks - 1)) {
            // Last block: old holds everyone else's sum; add our own contribution.
            unsigned long long total = (old & SUM_MASK) + (v & SUM_MASK);
            out[0] = (float)((double)total * (1.0 / FP_SCALE)) * inv_n;
            atomicExch(&g_acc, 0ull);    // reset for next graph replay
        }
    }
}

extern "C" void kernel_launch(void* const* d_in, const int* in_sizes, int n_in,
                              void* d_out, int out_size)
{
    const float* pred   = (const float*)d_in[0];
    const float* target = (const float*)d_in[1];
    const float* weight = (const float*)d_in[2];
    int N = in_sizes[2];

    int grid = (N + BLOCK - 1) / BLOCK;   // 4096 for N=1M

    iou3d_fused_kernel<<<grid, BLOCK>>>(pred, target, weight, (float*)d_out,
                                        N, 1.0f / (float)N, grid);
}

// round 6
// speedup vs baseline: 2.2015x; 1.2369x over previous
#include <cuda_runtime.h>

// IoU3DLoss: per-pair rotated 3D IoU -> mean((1-iou)*weight)
// Key identities:
//   cross(P+tmin*D, P+tmax*D) = (tmax-tmin)*cross(P,D)   -> no endpoint evaluation
//   B's own edges are axis-aligned in B's frame -> cross(P,D) = 2*W2*H2 for all 4
//   opposite rect edges have negated dirs -> share reciprocals (8 RCPs, not 16)
// 2 elements/thread via float2 loads (56B record pair is 8B-aligned).
// Fence-free deterministic reduction: one packed u64 atomicAdd
//   bits[0,44) = sum * 2^23 (integer adds associative), bits[44,64) = block counter.

constexpr int BLOCK = 256;
constexpr double FP_SCALE = 8388608.0;            // 2^23
constexpr unsigned long long SUM_MASK = (1ull << 44) - 1ull;
constexpr unsigned long long CNT_ONE  = 1ull << 44;

__device__ unsigned long long g_acc = 0ull;       // reset by last block each launch

// Length of the t-interval where P + t*D stays inside |u|<=W, |v|<=H, t in [0,1].
// (u0,v0) = start in box-local coords; (idu,idv) = reciprocals of local direction.
__device__ __forceinline__ float clip_dt(float u0, float v0, float idu, float idv,
                                         float W, float H)
{
    float ta = (-W - u0) * idu, tb = (W - u0) * idu;
    float lo1 = fminf(ta, tb), hi1 = fmaxf(ta, tb);
    float tc = (-H - v0) * idv, td = (H - v0) * idv;
    float lo2 = fminf(tc, td), hi2 = fmaxf(tc, td);
    float tmin = fmaxf(fmaxf(lo1, lo2), 0.0f);
    float tmax = fminf(fminf(hi1, hi2), 1.0f);
    return fmaxf(tmax - tmin, 0.0f);
}

__device__ __forceinline__ float pair_loss(
    float x1, float y1, float z1, float w1, float h1, float d1, float a1,
    float x2, float y2, float z2, float w2, float h2, float d2, float a2,
    float wgt)
{
    // B(target) local frame: B = axis box [+-W2,+-H2]; A at rel angle ar = a1-a2.
    float s2, c2; __sincosf(a2, &s2, &c2);
    float sr, cr; __sincosf(a1 - a2, &sr, &cr);

    float dx0 = x1 - x2, dy0 = y1 - y2;
    float cx =  c2 * dx0 + s2 * dy0;
    float cy = -s2 * dx0 + c2 * dy0;

    float W1 = 0.5f * w1, H1 = 0.5f * h1;
    float W2 = 0.5f * w2, H2 = 0.5f * h2;

    float ex = cr * W1, ey = sr * W1;     // A half-edges in B frame
    float fx = -sr * H1, fy = cr * H1;

    // A corners, CCW
    float Ax0 = cx + ex + fx, Ay0 = cy + ey + fy;
    float Ax1 = cx - ex + fx, Ay1 = cy - ey + fy;
    float Ax2 = cx - ex - fx, Ay2 = cy - ey - fy;
    float Ax3 = cx + ex - fx, Ay3 = cy + ey - fy;

    // Full edge vectors: A0->A1 = E, A1->A2 = F; A2->A3 = -E, A3->A0 = -F
    float Ex = Ax1 - Ax0, Ey = Ay1 - Ay0;
    float Fx = Ax2 - Ax1, Fy = Ay2 - Ay1;
    float iEx = __fdividef(1.0f, Ex), iEy = __fdividef(1.0f, Ey);
    float iFx = __fdividef(1.0f, Fx), iFy = __fdividef(1.0f, Fy);

    float area2;
    {   // Edges of A clipped by box B; contribution = dt * cross(P, D)
        float dt0 = clip_dt(Ax0, Ay0,  iEx,  iEy, W2, H2);
        float dt1 = clip_dt(Ax1, Ay1,  iFx,  iFy, W2, H2);
        float dt2 = clip_dt(Ax2, Ay2, -iEx, -iEy, W2, H2);
        float dt3 = clip_dt(Ax3, Ay3, -iFx, -iFy, W2, H2);
        float cr0 =  (Ax0 * Ey - Ay0 * Ex);
        float cr1 =  (Ax1 * Fy - Ay1 * Fx);
        float cr2 = -(Ax2 * Ey - Ay2 * Ex);
        float cr3 = -(Ax3 * Fy - Ay3 * Fx);
        area2 = dt0 * cr0 + dt1 * cr1 + dt2 * cr2 + dt3 * cr3;
    }
    {   // Edges of B clipped by box A; every edge has cross(P,D) = 2*W2*H2
        float a = cr * W2, c = sr * W2;   // A-local images of B's axes
        float b = sr * H2, d = cr * H2;
        float cu =  cr * cx + sr * cy;
        float cv = -sr * cx + cr * cy;
        // B corners (+-W2,+-H2) in A-local coords
        float u0 =  a + b - cu, v0 = -c + d - cv;   // ( W2,  H2)
        float u1 = -a + b - cu, v1 =  c + d - cv;   // (-W2,  H2)
        float u2 = -a - b - cu, v2 =  c - d - cv;   // (-W2, -H2)
        float u3 =  a - b - cu, v3 = -c - d - cv;   // ( W2, -H2)
        // Edge dirs in A-local: g0 = (-2a, 2c) (corners 0->1), g1 = (-2b, -2d) (1->2)
        float ig0x = __fdividef(1.0f, -2.0f * a), ig0y = __fdividef(1.0f,  2.0f * c);
        float ig1x = __fdividef(1.0f, -2.0f * b), ig1y = __fdividef(1.0f, -2.0f * d);
        float dts = clip_dt(u0, v0,  ig0x,  ig0y, W1, H1)
                  + clip_dt(u1, v1,  ig1x,  ig1y, W1, H1)
                  + clip_dt(u2, v2, -ig0x, -ig0y, W1, H1)
                  + clip_dt(u3, v3, -ig1x, -ig1y, W1, H1);
        area2 += (2.0f * W2 * H2) * dts;
    }

    float inter2d = 0.5f * fabsf(area2);

    float zmax = fminf(z1 + 0.5f * d1, z2 + 0.5f * d2);
    float zmin = fmaxf(z1 - 0.5f * d1, z2 - 0.5f * d2);
    float inter3d = inter2d * fmaxf(zmax - zmin, 0.0f);

    float v1 = w1 * h1 * d1;
    float v2 = w2 * h2 * d2;
    float iou = inter3d / (v1 + v2 - inter3d + 1e-8f);
    return (1.0f - iou) * wgt;
}

__global__ void __launch_bounds__(BLOCK)
iou3d_fused_kernel(const float* __restrict__ pred,
                   const float* __restrict__ target,
                   const float* __restrict__ weight,
                   float* __restrict__ out,
                   int N, float inv_n, int nblocks)
{
    __shared__ float swarp[BLOCK / 32];

    unsigned int t  = blockIdx.x * BLOCK + threadIdx.x;
    unsigned int i0 = 2u * t;
    float loss = 0.0f;

    if (i0 + 1u < (unsigned int)N) {
        // Record pair [i0, i0+1] = 14 floats = 7 float2 (8B-aligned: 56B * t)
        const float2* p2 = (const float2*)pred   + 7u * t;
        const float2* t2 = (const float2*)target + 7u * t;
        float2 P0 = p2[0], P1 = p2[1], P2 = p2[2], P3 = p2[3], P4 = p2[4], P5 = p2[5], P6 = p2[6];
        float2 T0 = t2[0], T1 = t2[1], T2 = t2[2], T3 = t2[3], T4 = t2[4], T5 = t2[5], T6 = t2[6];
        float2 Wt = ((const float2*)weight)[t];

        loss  = pair_loss(P0.x, P0.y, P1.x, P1.y, P2.x, P2.y, P3.x,
                          T0.x, T0.y, T1.x, T1.y, T2.x, T2.y, T3.x, Wt.x);
        loss += pair_loss(P3.y, P4.x, P4.y, P5.x, P5.y, P6.x, P6.y,
                          T3.y, T4.x, T4.y, T5.x, T5.y, T6.x, T6.y, Wt.y);
    } else if (i0 < (unsigned int)N) {
        // Odd tail element (never taken for N = 2^20, kept for generality)
        const float* b1 = pred   + 7u * i0;
        const float* b2 = target + 7u * i0;
        loss = pair_loss(b1[0], b1[1], b1[2], b1[3], b1[4], b1[5], b1[6],
                         b2[0], b2[1], b2[2], b2[3], b2[4], b2[5], b2[6],
                         weight[i0]);
    }

    // Block reduction: warp shuffle -> shared -> thread 0
    #pragma unroll
    for (int off = 16; off > 0; off >>= 1)
        loss += __shfl_xor_sync(0xffffffffu, loss, off);
    if ((threadIdx.x & 31) == 0) swarp[threadIdx.x >> 5] = loss;
    __syncthreads();

    if (threadIdx.x == 0) {
        float partial = 0.0f;
        #pragma unroll
        for (int w = 0; w < BLOCK / 32; w++) partial += swarp[w];

        unsigned long long v =
            (unsigned long long)((double)partial * FP_SCALE + 0.5) | CNT_ONE;
        unsigned long long old = atomicAdd(&g_acc, v);

        if ((old >> 44) == (unsigned long long)(nblocks - 1)) {
            unsigned long long total = (old & SUM_MASK) + (v & SUM_MASK);
            out[0] = (float)((double)total * (1.0 / FP_SCALE)) * inv_n;
            atomicExch(&g_acc, 0ull);    // reset for next graph replay
        }
    }
}

extern "C" void kernel_launch(void* const* d_in, const int* in_sizes, int n_in,
                              void* d_out, int out_size)
{
    const float* pred   = (const float*)d_in[0];
    const float* target = (const float*)d_in[1];
    const float* weight = (const float*)d_in[2];
    int N = in_sizes[2];

    int grid = (N + 2 * BLOCK - 1) / (2 * BLOCK);   // 2048 for N=1M

    iou3d_fused_kernel<<<grid, BLOCK>>>(pred, target, weight, (float*)d_out,
                                        N, 1.0f / (float)N, grid);
}